// round 2
// baseline (speedup 1.0000x reference)
#include <cuda_runtime.h>
#include <math.h>

#define NDIM 64
#define NB 64
#define MAXT 512
#define PAD 65
#define NMAT (NDIM*PAD)
#define HL2PI 0.91893853320467274178f
#define SMEM_BYTES (9*NMAT*4)

// ---------------- static device scratch (no runtime allocation) ----------------
__device__ float g_KT[(MAXT+1)*NDIM*NDIM];     // K^T per step, k-major: [t][k*64+j] = K[j][k]
__device__ float g_LinvT[(MAXT+1)*NDIM*NDIM];  // (L^-1)^T per step: [t][k*64+j] = Linv[j][k]
__device__ float g_postP[(MAXT+1)*NDIM*NDIM];  // posterior covariance per step (row-major 64x64)
__device__ float g_pref[MAXT+1];               // -dy*0.5*log(2pi) - 0.5*logdet(S_t)
__device__ int   g_tfreeze;

// ---------------- 64x64 matmul on PAD-strided smem, 256 threads ----------------
// C = Cadd + sgn * op(A) @ op(B); TA/TB select transpose of the smem operand.
template<bool TA, bool TB>
__device__ __forceinline__ void mm64(float* C, const float* A, const float* B,
                                     const float* Cadd, float sgn)
{
    const int tid = threadIdx.x;
    const int i0 = (tid >> 4) << 2;
    const int j0 = (tid & 15) << 2;
    float acc[4][4];
#pragma unroll
    for (int r = 0; r < 4; r++)
#pragma unroll
        for (int c = 0; c < 4; c++) acc[r][c] = 0.f;
#pragma unroll 4
    for (int k = 0; k < NDIM; k++) {
        float a[4], b[4];
#pragma unroll
        for (int r = 0; r < 4; r++) a[r] = TA ? A[k*PAD + (i0+r)] : A[(i0+r)*PAD + k];
#pragma unroll
        for (int c = 0; c < 4; c++) b[c] = TB ? B[(j0+c)*PAD + k] : B[k*PAD + (j0+c)];
#pragma unroll
        for (int r = 0; r < 4; r++)
#pragma unroll
            for (int c = 0; c < 4; c++) acc[r][c] += a[r] * b[c];
    }
#pragma unroll
    for (int r = 0; r < 4; r++)
#pragma unroll
        for (int c = 0; c < 4; c++) {
            float base = Cadd ? Cadd[(i0+r)*PAD + (j0+c)] : 0.f;
            C[(i0+r)*PAD + (j0+c)] = base + sgn * acc[r][c];
        }
}

__device__ __forceinline__ void ld_mat(float* dst, const float* __restrict__ src) {
    for (int idx = threadIdx.x; idx < NDIM*NDIM; idx += blockDim.x)
        dst[(idx >> 6)*PAD + (idx & 63)] = src[idx];
}

// =======================================================================
// Phase 1: sequential Riccati recursion (covariances, gains, log-dets).
// Single CTA, 256 threads. Freezes once the posterior covariance is
// stationary to <1e-6 (contraction => typically converges in tens of steps).
// =======================================================================
__global__ void riccati_kernel(const float* __restrict__ prior_chol,
                               const float* __restrict__ Fw,
                               const float* __restrict__ dyn_chol,
                               const float* __restrict__ Hw,
                               const float* __restrict__ obs_chol,
                               int T)
{
    extern __shared__ float sm[];
    float* sP  = sm + 0*NMAT;   // carries P -> pP -> postP
    float* sT  = sm + 1*NMAT;   // temp
    float* sCW = sm + 2*NMAT;   // CW then K^T
    float* sL  = sm + 3*NMAT;   // S then chol(L)
    float* sLi = sm + 4*NMAT;   // L^-1
    float* sF  = sm + 5*NMAT;
    float* sH  = sm + 6*NMAT;
    float* sQ  = sm + 7*NMAT;
    float* sR  = sm + 8*NMAT;
    __shared__ float s_red[256];
    __shared__ float s_dinv[NDIM];
    __shared__ float s_log[NDIM];
    __shared__ float s_scalar;

    const int tid = threadIdx.x;

    ld_mat(sF, Fw); ld_mat(sH, Hw); ld_mat(sT, dyn_chol);
    __syncthreads();
    mm64<false,true>(sQ, sT, sT, nullptr, 1.f);    // Q = Lq Lq^T
    __syncthreads();
    ld_mat(sT, obs_chol);
    __syncthreads();
    mm64<false,true>(sR, sT, sT, nullptr, 1.f);    // R = Lr Lr^T
    __syncthreads();
    ld_mat(sT, prior_chol);
    __syncthreads();
    mm64<false,true>(sP, sT, sT, nullptr, 1.f);    // P0 (predictive cov for t=0)
    __syncthreads();

    int tf = T;
    for (int t = 0; t <= T; t++) {
        if (t > 0) {
            mm64<false,false>(sT, sF, sP, nullptr, 1.f);   // T1 = F P
            __syncthreads();
            mm64<false,true>(sP, sT, sF, sQ, 1.f);         // pP = T1 F^T + Q
            __syncthreads();
        }
        mm64<false,true>(sCW, sP, sH, nullptr, 1.f);       // CW = pP H^T
        __syncthreads();
        mm64<false,false>(sL, sH, sCW, sR, 1.f);           // S = H CW + R
        __syncthreads();

        // ---- Cholesky of S (lower, in place) ----
        for (int c = 0; c < NDIM; c++) {
            if (tid == 0) {
                float d = sqrtf(sL[c*PAD + c]);
                sL[c*PAD + c] = d;
                s_scalar = 1.0f / d;
            }
            __syncthreads();
            float dinv = s_scalar;
            for (int r = c + 1 + tid; r < NDIM; r += blockDim.x) sL[r*PAD + c] *= dinv;
            __syncthreads();
            int n = NDIM - 1 - c;
            for (int idx = tid; idx < n*n; idx += blockDim.x) {
                int rr = idx / n;
                int r = c + 1 + rr;
                int j = c + 1 + (idx - rr*n);
                sL[r*PAD + j] -= sL[r*PAD + c] * sL[j*PAD + c];
            }
            __syncthreads();
        }
        if (tid < NDIM) {
            float d = sL[tid*PAD + tid];
            s_dinv[tid] = 1.0f / d;
            s_log[tid]  = logf(d);
        }
        __syncthreads();
        if (tid == 0) {
            float s = 0.f;
            for (int i = 0; i < NDIM; i++) s += s_log[i];
            g_pref[t] = -NDIM * HL2PI - s;
        }

        // ---- Linv = L^-1 (each thread owns one column; forward substitution) ----
        if (tid < NDIM) {
            int c = tid;
            for (int r = 0; r < NDIM; r++) {
                float s = (r == c) ? 1.f : 0.f;
                for (int k = c; k < r; k++) s -= sL[r*PAD + k] * sLi[k*PAD + c];
                sLi[r*PAD + c] = s * s_dinv[r];   // zero for r<c automatically
            }
        }
        __syncthreads();

        mm64<false,true>(sT, sLi, sCW, nullptr, 1.f);      // t2 = Linv CW^T
        __syncthreads();
        mm64<true,false>(sCW, sLi, sT, nullptr, 1.f);      // K^T = Linv^T t2
        __syncthreads();
        mm64<true,false>(sP, sT, sT, sP, -1.f);            // postP = pP - t2^T t2
        __syncthreads();

        // ---- store per-t matrices + convergence metric ----
        float mymax = 0.f;
        const size_t off = (size_t)t * NDIM * NDIM;
        for (int idx = tid; idx < NDIM*NDIM; idx += blockDim.x) {
            int i = idx >> 6, j = idx & 63;
            float v = sP[i*PAD + j];
            if (t >= 1) mymax = fmaxf(mymax, fabsf(v - g_postP[off - NDIM*NDIM + idx]));
            g_postP[off + idx] = v;
            g_KT[off + idx]    = sCW[i*PAD + j];   // already K^T, row-major (k-major)
            g_LinvT[off + idx] = sLi[j*PAD + i];   // (L^-1)^T, k-major
        }
        s_red[tid] = mymax;
        __syncthreads();
        for (int s = 128; s > 0; s >>= 1) {
            if (tid < s) s_red[tid] = fmaxf(s_red[tid], s_red[tid + s]);
            __syncthreads();
        }
        if (t >= 1 && s_red[0] < 1e-6f) { tf = t; break; }
        __syncthreads();
    }
    if (tid == 0) g_tfreeze = tf;
}

// =======================================================================
// Phase 2: per-batch mean & likelihood recursion.
// 64 blocks (one per batch row) x 64 threads (one per state/obs component).
// =======================================================================
__global__ void means_kernel(const float* __restrict__ obs,
                             const float* __restrict__ Fw,
                             const float* __restrict__ Hw,
                             const float* __restrict__ pm0,
                             const float* __restrict__ db,
                             const float* __restrict__ ob,
                             float* __restrict__ out_means,
                             float* __restrict__ out_ll,
                             int T)
{
    __shared__ float WF[NDIM*NDIM];   // WF[k*64+j] = F[j][k]
    __shared__ float WH[NDIM*NDIM];   // WH[k*64+j] = H[j][k]
    __shared__ float vm[NDIM], vpm[NDIM], vr[NDIM];
    __shared__ float sred[2];

    const int j = threadIdx.x;
    const int b = blockIdx.x;

    for (int k = 0; k < NDIM; k++) {
        WF[k*NDIM + j] = Fw[j*NDIM + k];
        WH[k*NDIM + j] = Hw[j*NDIM + k];
    }
    const int tf = g_tfreeze;
    const float dbj = db[j], obj = ob[j];
    __syncthreads();

    for (int t = 0; t <= T; t++) {
        float pm;
        if (t == 0) {
            pm = pm0[j];
        } else {
            float a = 0.f;
#pragma unroll 8
            for (int k = 0; k < NDIM; k++) a += vm[k] * WF[k*NDIM + j];
            pm = a + dbj;
        }
        vpm[j] = pm;
        __syncthreads();

        float o = 0.f;
#pragma unroll 8
        for (int k = 0; k < NDIM; k++) o += vpm[k] * WH[k*NDIM + j];
        float r = obs[((size_t)t * NB + b) * NDIM + j] - o - obj;
        vr[j] = r;
        __syncthreads();

        const int tc = (t < tf) ? t : tf;
        const float* KTp = g_KT    + (size_t)tc * NDIM * NDIM;
        const float* LTp = g_LinvT + (size_t)tc * NDIM * NDIM;
        float mu = 0.f, z = 0.f;
#pragma unroll 8
        for (int k = 0; k < NDIM; k++) {
            float rv = vr[k];
            mu += rv * KTp[k*NDIM + j];
            z  += rv * LTp[k*NDIM + j];
        }
        float mnew = pm + mu;
        out_means[((size_t)t * NB + b) * NDIM + j] = mnew;
        vm[j] = mnew;

        float q = z * z;
#pragma unroll
        for (int o2 = 16; o2 > 0; o2 >>= 1) q += __shfl_down_sync(0xffffffffu, q, o2);
        if ((j & 31) == 0) sred[j >> 5] = q;
        __syncthreads();
        if (j == 0)
            out_ll[(size_t)t * NB + b] = g_pref[tc] - 0.5f * (sred[0] + sred[1]);
        __syncthreads();
    }
}

// =======================================================================
// Phase 3: broadcast covariance matrices to the (T+1, B, 64, 64) output.
// =======================================================================
__global__ void bcast_cov(float* __restrict__ out_covs, int T)
{
    const int tf = g_tfreeze;
    const int blk = blockIdx.x;           // blk = t*NB + b
    const int t = blk >> 6;
    const int tc = (t < tf) ? t : tf;
    const float4* src = (const float4*)(g_postP + (size_t)tc * NDIM * NDIM);
    float4* dst = (float4*)(out_covs + (size_t)blk * NDIM * NDIM);
    for (int i = threadIdx.x; i < (NDIM*NDIM)/4; i += blockDim.x) dst[i] = src[i];
}

// =======================================================================
extern "C" void kernel_launch(void* const* d_in, const int* in_sizes, int n_in,
                              void* d_out, int out_size)
{
    int base = n_in - 9;          // handles time_extent scalar present (n_in=10) or not
    if (base < 0) base = 0;

    const float* obs = (const float*)d_in[base + 0];  // observation (T+1, B, DY)
    const float* pm0 = (const float*)d_in[base + 1];  // prior_mean (DX)
    const float* pc  = (const float*)d_in[base + 2];  // prior_chol
    const float* Fw  = (const float*)d_in[base + 3];  // dynamic_weight
    const float* db  = (const float*)d_in[base + 4];  // dynamic_bias
    const float* dc  = (const float*)d_in[base + 5];  // dynamic_chol
    const float* Hw  = (const float*)d_in[base + 6];  // observation_weight
    const float* ob  = (const float*)d_in[base + 7];  // observation_bias
    const float* oc  = (const float*)d_in[base + 8];  // observation_chol

    int T = in_sizes[base + 0] / (NB * NDIM) - 1;
    if (T > MAXT) T = MAXT;
    if (T < 1) T = 1;

    float* out_means = (float*)d_out;
    float* out_covs  = out_means + (size_t)(T + 1) * NB * NDIM;
    float* out_ll    = out_covs  + (size_t)(T + 1) * NB * NDIM * NDIM;

    cudaFuncSetAttribute(riccati_kernel,
                         cudaFuncAttributeMaxDynamicSharedMemorySize, SMEM_BYTES);

    riccati_kernel<<<1, 256, SMEM_BYTES>>>(pc, Fw, dc, Hw, oc, T);
    means_kernel<<<NB, NDIM>>>(obs, Fw, Hw, pm0, db, ob, out_means, out_ll, T);
    bcast_cov<<<(T + 1) * NB, 256>>>(out_covs, T);
}

// round 3
// speedup vs baseline: 3.1493x; 3.1493x over previous
#include <cuda_runtime.h>
#include <math.h>

#define NDIM 64
#define NB 64
#define MAXT 512
#define PAD 65
#define NMAT (NDIM*PAD)
#define HL2PI 0.91893853320467274178f
#define R_SMEM (10*NMAT*4)
#define M_SMEM (4*NDIM*NDIM*4)

// ---------------- static device scratch ----------------
__device__ float g_KT[(MAXT+1)*NDIM*NDIM];     // K^T per step: [t][k*64+j] = K[j][k]
__device__ float g_SI[(MAXT+1)*NDIM*NDIM];     // S^-1 per step (symmetric, row-major)
__device__ float g_postP[(MAXT+1)*NDIM*NDIM];  // posterior covariance per step
__device__ float g_pref[MAXT+1];
__device__ float g_WFT[NDIM*NDIM];             // [k*64+j] = F[j][k]
__device__ float g_WHFT[NDIM*NDIM];            // [k*64+j] = (H@F)[j][k]
__device__ float g_c2[NDIM];                   // (H db + ob)
__device__ float g_o0[NDIM];                   // pm0 H^T + ob
__device__ int   g_tfreeze;

// ---------------- 64x64 matmul on PAD-strided smem, 256 threads ----------------
template<bool TA, bool TB>
__device__ __forceinline__ void mm64(float* C, const float* A, const float* B,
                                     const float* Cadd, float sgn)
{
    const int tid = threadIdx.x;
    const int i0 = (tid >> 4) << 2;
    const int j0 = (tid & 15) << 2;
    float acc[4][4];
#pragma unroll
    for (int r = 0; r < 4; r++)
#pragma unroll
        for (int c = 0; c < 4; c++) acc[r][c] = 0.f;
#pragma unroll 4
    for (int k = 0; k < NDIM; k++) {
        float a[4], b[4];
#pragma unroll
        for (int r = 0; r < 4; r++) a[r] = TA ? A[k*PAD + (i0+r)] : A[(i0+r)*PAD + k];
#pragma unroll
        for (int c = 0; c < 4; c++) b[c] = TB ? B[(j0+c)*PAD + k] : B[k*PAD + (j0+c)];
#pragma unroll
        for (int r = 0; r < 4; r++)
#pragma unroll
            for (int c = 0; c < 4; c++) acc[r][c] += a[r] * b[c];
    }
#pragma unroll
    for (int r = 0; r < 4; r++)
#pragma unroll
        for (int c = 0; c < 4; c++) {
            float base = Cadd ? Cadd[(i0+r)*PAD + (j0+c)] : 0.f;
            C[(i0+r)*PAD + (j0+c)] = base + sgn * acc[r][c];
        }
}

__device__ __forceinline__ void ld_mat(float* dst, const float* __restrict__ src) {
    for (int idx = threadIdx.x; idx < NDIM*NDIM; idx += blockDim.x)
        dst[(idx >> 6)*PAD + (idx & 63)] = src[idx];
}

// =======================================================================
// Phase 1: Riccati recursion with Gauss-Jordan S-inversion, freezes on
// covariance stationarity. One CTA, 256 threads.
// =======================================================================
__global__ void riccati_kernel(const float* __restrict__ prior_chol,
                               const float* __restrict__ Fw,
                               const float* __restrict__ dyn_chol,
                               const float* __restrict__ Hw,
                               const float* __restrict__ obs_chol,
                               const float* __restrict__ pm0,
                               const float* __restrict__ db,
                               const float* __restrict__ ob,
                               int T)
{
    extern __shared__ float sm[];
    float* sP    = sm + 0*NMAT;
    float* sT    = sm + 1*NMAT;
    float* sCW   = sm + 2*NMAT;
    float* sSa   = sm + 3*NMAT;
    float* sSb   = sm + 4*NMAT;
    float* sF    = sm + 5*NMAT;
    float* sH    = sm + 6*NMAT;
    float* sQ    = sm + 7*NMAT;
    float* sR    = sm + 8*NMAT;
    float* sPrev = sm + 9*NMAT;
    __shared__ float s_red[256];
    __shared__ float s_piv[NDIM];
    __shared__ float s_log[NDIM];

    const int tid = threadIdx.x;

    ld_mat(sF, Fw); ld_mat(sH, Hw); ld_mat(sT, dyn_chol);
    __syncthreads();
    mm64<false,true>(sQ, sT, sT, nullptr, 1.f);
    __syncthreads();
    ld_mat(sT, obs_chol);
    __syncthreads();
    mm64<false,true>(sR, sT, sT, nullptr, 1.f);
    __syncthreads();
    ld_mat(sT, prior_chol);
    __syncthreads();
    mm64<false,true>(sP, sT, sT, nullptr, 1.f);
    __syncthreads();

    // Precompute merged matrices/vectors for the means kernel
    mm64<false,false>(sT, sH, sF, nullptr, 1.f);   // HF
    __syncthreads();
    for (int idx = tid; idx < NDIM*NDIM; idx += blockDim.x) {
        int k = idx >> 6, j = idx & 63;
        g_WHFT[idx] = sT[j*PAD + k];
        g_WFT[idx]  = sF[j*PAD + k];
    }
    if (tid < NDIM) {
        float c = 0.f, o0 = 0.f;
        for (int k = 0; k < NDIM; k++) {
            float h = sH[tid*PAD + k];
            c  += h * db[k];
            o0 += h * pm0[k];
        }
        g_c2[tid] = c + ob[tid];
        g_o0[tid] = o0 + ob[tid];
    }
    __syncthreads();

    int tf = T;
    for (int t = 0; t <= T; t++) {
        if (t > 0) {
            mm64<false,false>(sT, sF, sP, nullptr, 1.f);  // T1 = F P
            __syncthreads();
            mm64<false,true>(sP, sT, sF, sQ, 1.f);        // pP = T1 F^T + Q
            __syncthreads();
        }
        mm64<false,true>(sCW, sP, sH, nullptr, 1.f);      // CW = pP H^T
        __syncthreads();
        mm64<false,false>(sSa, sH, sCW, sR, 1.f);         // S = H CW + R
        __syncthreads();

        // ---- Gauss-Jordan inversion of S (ping-pong, 1 sync per pivot) ----
        {
            float* A = sSa; float* Bm = sSb;
            for (int p = 0; p < NDIM; p++) {
                float piv = A[p*PAD + p];
                float d = 1.0f / piv;
                if (tid == 0) s_piv[p] = piv;
#pragma unroll
                for (int e = 0; e < 16; e++) {
                    int idx = tid + e*256;
                    int i = idx >> 6, j = idx & 63;
                    float aij = A[i*PAD + j];
                    float aip = A[i*PAD + p];
                    float apj = A[p*PAD + j];
                    float v;
                    if (i == p) v = (j == p) ? d : apj * d;
                    else if (j == p) v = -aip * d;
                    else v = aij - aip * apj * d;
                    Bm[i*PAD + j] = v;
                }
                __syncthreads();
                float* tmp = A; A = Bm; Bm = tmp;
            }
            // 64 swaps (even) => result back in sSa
        }
        if (tid < NDIM) s_log[tid] = logf(s_piv[tid]);
        __syncthreads();
        if (tid == 0) {
            float s = 0.f;
            for (int i = 0; i < NDIM; i++) s += s_log[i];
            g_pref[t] = -NDIM * HL2PI - 0.5f * s;
        }

        mm64<true,true>(sT, sSa, sCW, nullptr, 1.f);      // KT[k][j] = sum_m Sinv[m][k] CW[j][m]
        __syncthreads();
        mm64<true,true>(sP, sT, sCW, sP, -1.f);           // postP = pP - K CW^T
        __syncthreads();

        // ---- store + convergence check (vs smem-cached previous P) ----
        float mymax = 0.f;
        const size_t off = (size_t)t * NDIM * NDIM;
        for (int idx = tid; idx < NDIM*NDIM; idx += blockDim.x) {
            int i = idx >> 6, j = idx & 63;
            float v = sP[i*PAD + j];
            if (t >= 1) mymax = fmaxf(mymax, fabsf(v - sPrev[i*PAD + j]));
            sPrev[i*PAD + j] = v;
            g_postP[off + idx] = v;
            g_KT[off + idx]    = sT[i*PAD + j];
            g_SI[off + idx]    = sSa[i*PAD + j];
        }
        s_red[tid] = mymax;
        __syncthreads();
        for (int s = 128; s > 0; s >>= 1) {
            if (tid < s) s_red[tid] = fmaxf(s_red[tid], s_red[tid + s]);
            __syncthreads();
        }
        if (t >= 1 && s_red[0] < 1e-6f) { tf = t; break; }
        __syncthreads();
    }
    if (tid == 0) g_tfreeze = tf;
}

// =======================================================================
// Phase 2: per-batch mean & likelihood recursion.
// 64 blocks x 64 threads. Frozen K/Sinv cached in shared memory.
// Fused F/H matvecs via precomputed HF (2 syncs per step).
// =======================================================================
__global__ void means_kernel(const float* __restrict__ obs,
                             const float* __restrict__ pm0,
                             const float* __restrict__ db,
                             float* __restrict__ out_means,
                             float* __restrict__ out_ll,
                             int T)
{
    extern __shared__ float ms[];
    float* sWFT  = ms;
    float* sWHFT = ms + 4096;
    float* sKT   = ms + 8192;
    float* sSI   = ms + 12288;
    __shared__ float vm[NDIM], vr[NDIM];
    __shared__ float sred[2];

    const int j = threadIdx.x;
    const int b = blockIdx.x;

    const int tf = g_tfreeze;
    {
        const float* KTf = g_KT + (size_t)tf * NDIM * NDIM;
        const float* SIf = g_SI + (size_t)tf * NDIM * NDIM;
        for (int idx = j; idx < NDIM*NDIM; idx += NDIM) {
            sWFT[idx]  = g_WFT[idx];
            sWHFT[idx] = g_WHFT[idx];
            sKT[idx]   = KTf[idx];
            sSI[idx]   = SIf[idx];
        }
    }
    const float pref_f = g_pref[tf];
    const float dbj = db[j];
    const float c2j = g_c2[j];
    const float o0j = g_o0[j];
    const float pm0j = pm0[j];
    __syncthreads();

    for (int t = 0; t <= T; t++) {
        float y = obs[((size_t)t * NB + b) * NDIM + j];
        float pm, o;
        if (t == 0) {
            pm = pm0j; o = o0j;
        } else {
            float a0 = 0.f, a1 = 0.f, c0 = 0.f, c1 = 0.f;
#pragma unroll
            for (int k = 0; k < NDIM; k += 2) {
                float v0 = vm[k], v1 = vm[k+1];
                a0 += v0 * sWFT [k*NDIM + j];
                c0 += v0 * sWHFT[k*NDIM + j];
                a1 += v1 * sWFT [(k+1)*NDIM + j];
                c1 += v1 * sWHFT[(k+1)*NDIM + j];
            }
            pm = a0 + a1 + dbj;
            o  = c0 + c1 + c2j;
        }
        float r = y - o;
        vr[j] = r;
        __syncthreads();

        float mu0 = 0.f, mu1 = 0.f, u0 = 0.f, u1 = 0.f;
        if (t >= tf) {
#pragma unroll
            for (int k = 0; k < NDIM; k += 2) {
                float r0 = vr[k], r1 = vr[k+1];
                mu0 += r0 * sKT[k*NDIM + j];
                u0  += r0 * sSI[k*NDIM + j];
                mu1 += r1 * sKT[(k+1)*NDIM + j];
                u1  += r1 * sSI[(k+1)*NDIM + j];
            }
        } else {
            const float* KTp = g_KT + (size_t)t * NDIM * NDIM;
            const float* SIp = g_SI + (size_t)t * NDIM * NDIM;
#pragma unroll 8
            for (int k = 0; k < NDIM; k += 2) {
                float r0 = vr[k], r1 = vr[k+1];
                mu0 += r0 * KTp[k*NDIM + j];
                u0  += r0 * SIp[k*NDIM + j];
                mu1 += r1 * KTp[(k+1)*NDIM + j];
                u1  += r1 * SIp[(k+1)*NDIM + j];
            }
        }
        float mu = mu0 + mu1, u = u0 + u1;
        float mnew = pm + mu;
        out_means[((size_t)t * NB + b) * NDIM + j] = mnew;
        vm[j] = mnew;

        float q = r * u;
#pragma unroll
        for (int o2 = 16; o2 > 0; o2 >>= 1) q += __shfl_down_sync(0xffffffffu, q, o2);
        if ((j & 31) == 0) sred[j >> 5] = q;
        __syncthreads();
        if (j == 0) {
            float pref = (t >= tf) ? pref_f : g_pref[t];
            out_ll[(size_t)t * NB + b] = pref - 0.5f * (sred[0] + sred[1]);
        }
    }
}

// =======================================================================
// Phase 3: broadcast covariances to (T+1, B, 64, 64) output.
// =======================================================================
__global__ void bcast_cov(float* __restrict__ out_covs, int T)
{
    const int tf = g_tfreeze;
    const int blk = blockIdx.x;           // blk = t*NB + b
    const int t = blk >> 6;
    const int tc = (t < tf) ? t : tf;
    const float4* src = (const float4*)(g_postP + (size_t)tc * NDIM * NDIM);
    float4* dst = (float4*)(out_covs + (size_t)blk * NDIM * NDIM);
#pragma unroll
    for (int e = 0; e < 8; e++)
        dst[threadIdx.x + e*128] = src[threadIdx.x + e*128];
}

// =======================================================================
extern "C" void kernel_launch(void* const* d_in, const int* in_sizes, int n_in,
                              void* d_out, int out_size)
{
    int base = n_in - 9;
    if (base < 0) base = 0;

    const float* obs = (const float*)d_in[base + 0];
    const float* pm0 = (const float*)d_in[base + 1];
    const float* pc  = (const float*)d_in[base + 2];
    const float* Fw  = (const float*)d_in[base + 3];
    const float* db  = (const float*)d_in[base + 4];
    const float* dc  = (const float*)d_in[base + 5];
    const float* Hw  = (const float*)d_in[base + 6];
    const float* ob  = (const float*)d_in[base + 7];
    const float* oc  = (const float*)d_in[base + 8];

    int T = in_sizes[base + 0] / (NB * NDIM) - 1;
    if (T > MAXT) T = MAXT;
    if (T < 1) T = 1;

    float* out_means = (float*)d_out;
    float* out_covs  = out_means + (size_t)(T + 1) * NB * NDIM;
    float* out_ll    = out_covs  + (size_t)(T + 1) * NB * NDIM * NDIM;

    cudaFuncSetAttribute(riccati_kernel,
                         cudaFuncAttributeMaxDynamicSharedMemorySize, R_SMEM);
    cudaFuncSetAttribute(means_kernel,
                         cudaFuncAttributeMaxDynamicSharedMemorySize, M_SMEM);

    riccati_kernel<<<1, 256, R_SMEM>>>(pc, Fw, dc, Hw, oc, pm0, db, ob, T);
    means_kernel<<<NB, NDIM, M_SMEM>>>(obs, pm0, db, out_means, out_ll, T);
    bcast_cov<<<(T + 1) * NB, 128>>>(out_covs, T);
}

// round 4
// speedup vs baseline: 8.1314x; 2.5819x over previous
#include <cuda_runtime.h>
#include <math.h>

#define NDIM 64
#define NB 64
#define MAXT 512
#define PAD 65
#define NMAT (NDIM*PAD)
#define HL2PI 0.91893853320467274178f
#define R_SMEM (9*NMAT*4)
#define M_SMEM ((8192+8192+4096)*4)

// ---------------- static device scratch ----------------
__device__ float g_KT[(MAXT+1)*NDIM*NDIM];     // K^T per step: [t][k*64+j] = K[j][k]
__device__ float g_SI[(MAXT+1)*NDIM*NDIM];     // S^-1 per step (symmetric)
__device__ float g_postP[(MAXT+1)*NDIM*NDIM];  // posterior covariance per step
__device__ float g_pref[MAXT+1];
__device__ float g_WFT[NDIM*NDIM];             // [k*64+j] = F[j][k]
__device__ float g_WHFT[NDIM*NDIM];            // [k*64+j] = (H@F)[j][k]
__device__ float g_c2[NDIM];                   // H db + ob
__device__ float g_o0[NDIM];                   // pm0 H^T + ob
__device__ int   g_tfreeze;

// ---------------- full 64x64 matmul on PAD-strided smem, 256 threads ----------------
template<bool TA, bool TB>
__device__ __forceinline__ void mm64(float* C, const float* A, const float* B,
                                     const float* Cadd, float sgn)
{
    const int tid = threadIdx.x;
    const int i0 = (tid >> 4) << 2;
    const int j0 = (tid & 15) << 2;
    float acc[4][4];
#pragma unroll
    for (int r = 0; r < 4; r++)
#pragma unroll
        for (int c = 0; c < 4; c++) acc[r][c] = 0.f;
#pragma unroll 4
    for (int k = 0; k < NDIM; k++) {
        float a[4], b[4];
#pragma unroll
        for (int r = 0; r < 4; r++) a[r] = TA ? A[k*PAD + (i0+r)] : A[(i0+r)*PAD + k];
#pragma unroll
        for (int c = 0; c < 4; c++) b[c] = TB ? B[(j0+c)*PAD + k] : B[k*PAD + (j0+c)];
#pragma unroll
        for (int r = 0; r < 4; r++)
#pragma unroll
            for (int c = 0; c < 4; c++) acc[r][c] += a[r] * b[c];
    }
#pragma unroll
    for (int r = 0; r < 4; r++)
#pragma unroll
        for (int c = 0; c < 4; c++) {
            float base = Cadd ? Cadd[(i0+r)*PAD + (j0+c)] : 0.f;
            C[(i0+r)*PAD + (j0+c)] = base + sgn * acc[r][c];
        }
}

// ---------------- symmetric-output matmul: only upper block-triangle + mirror ----
template<bool TA, bool TB>
__device__ __forceinline__ void mm64_sym(float* C, const float* A, const float* B,
                                         const float* Cadd, float sgn,
                                         int i0, int j0, bool act)
{
    if (!act) return;
    float acc[4][4];
#pragma unroll
    for (int r = 0; r < 4; r++)
#pragma unroll
        for (int c = 0; c < 4; c++) acc[r][c] = 0.f;
#pragma unroll 4
    for (int k = 0; k < NDIM; k++) {
        float a[4], b[4];
#pragma unroll
        for (int r = 0; r < 4; r++) a[r] = TA ? A[k*PAD + (i0+r)] : A[(i0+r)*PAD + k];
#pragma unroll
        for (int c = 0; c < 4; c++) b[c] = TB ? B[(j0+c)*PAD + k] : B[k*PAD + (j0+c)];
#pragma unroll
        for (int r = 0; r < 4; r++)
#pragma unroll
            for (int c = 0; c < 4; c++) acc[r][c] += a[r] * b[c];
    }
#pragma unroll
    for (int r = 0; r < 4; r++)
#pragma unroll
        for (int c = 0; c < 4; c++) {
            float base = Cadd ? Cadd[(i0+r)*PAD + (j0+c)] : 0.f;
            float v = base + sgn * acc[r][c];
            C[(i0+r)*PAD + (j0+c)] = v;
            if (i0 != j0) C[(j0+c)*PAD + (i0+r)] = v;
        }
}

__device__ __forceinline__ void ld_mat(float* dst, const float* __restrict__ src) {
    for (int idx = threadIdx.x; idx < NDIM*NDIM; idx += blockDim.x)
        dst[(idx >> 6)*PAD + (idx & 63)] = src[idx];
}

// =======================================================================
// Phase 1: Riccati recursion. One CTA, 256 threads.
// Register-resident Gauss-Jordan, symmetric matmuls halved.
// =======================================================================
__global__ void riccati_kernel(const float* __restrict__ prior_chol,
                               const float* __restrict__ Fw,
                               const float* __restrict__ dyn_chol,
                               const float* __restrict__ Hw,
                               const float* __restrict__ obs_chol,
                               const float* __restrict__ pm0,
                               const float* __restrict__ db,
                               const float* __restrict__ ob,
                               int T)
{
    extern __shared__ float sm[];
    float* sP    = sm + 0*NMAT;
    float* sT    = sm + 1*NMAT;
    float* sCW   = sm + 2*NMAT;
    float* sSa   = sm + 3*NMAT;
    float* sF    = sm + 4*NMAT;
    float* sH    = sm + 5*NMAT;
    float* sQ    = sm + 6*NMAT;
    float* sR    = sm + 7*NMAT;
    float* sPrev = sm + 8*NMAT;
    __shared__ float s_red[256];
    __shared__ float s_row[2][NDIM];
    __shared__ float s_col[2][NDIM];

    const int tid = threadIdx.x;
    const int gi0 = (tid >> 4) << 2;
    const int gj0 = (tid & 15) << 2;

    // upper block-triangle mapping for symmetric matmuls
    int sbi = -1, sbj = 0;
    {
        int acc = 0;
#pragma unroll
        for (int r = 0; r < 16; r++) {
            int cnt = 16 - r;
            if (tid >= acc && tid < acc + cnt) { sbi = r; sbj = r + (tid - acc); }
            acc += cnt;
        }
    }
    const bool s_act = (sbi >= 0);
    const int si0 = sbi << 2, sj0 = sbj << 2;

    ld_mat(sF, Fw); ld_mat(sH, Hw); ld_mat(sT, dyn_chol);
    __syncthreads();
    mm64_sym<false,true>(sQ, sT, sT, nullptr, 1.f, si0, sj0, s_act);
    __syncthreads();
    ld_mat(sT, obs_chol);
    __syncthreads();
    mm64_sym<false,true>(sR, sT, sT, nullptr, 1.f, si0, sj0, s_act);
    __syncthreads();
    ld_mat(sT, prior_chol);
    __syncthreads();
    mm64_sym<false,true>(sP, sT, sT, nullptr, 1.f, si0, sj0, s_act);
    __syncthreads();

    // precompute for means kernel
    mm64<false,false>(sT, sH, sF, nullptr, 1.f);   // HF
    __syncthreads();
    for (int idx = tid; idx < NDIM*NDIM; idx += blockDim.x) {
        int k = idx >> 6, j = idx & 63;
        g_WHFT[idx] = sT[j*PAD + k];
        g_WFT[idx]  = sF[j*PAD + k];
    }
    if (tid < NDIM) {
        float c = 0.f, o0 = 0.f;
        for (int k = 0; k < NDIM; k++) {
            float h = sH[tid*PAD + k];
            c  += h * db[k];
            o0 += h * pm0[k];
        }
        g_c2[tid] = c + ob[tid];
        g_o0[tid] = o0 + ob[tid];
    }
    __syncthreads();

    int tf = T;
    for (int t = 0; t <= T; t++) {
        if (t > 0) {
            mm64<false,false>(sT, sF, sP, nullptr, 1.f);             // T1 = F P
            __syncthreads();
            mm64_sym<false,true>(sP, sT, sF, sQ, 1.f, si0, sj0, s_act); // pP
            __syncthreads();
        }
        mm64<false,true>(sCW, sP, sH, nullptr, 1.f);                 // CW = pP H^T
        __syncthreads();
        mm64_sym<false,false>(sSa, sH, sCW, sR, 1.f, si0, sj0, s_act); // S
        __syncthreads();

        // ---- register-resident Gauss-Jordan inversion of S ----
        {
            float a[4][4];
#pragma unroll
            for (int r = 0; r < 4; r++)
#pragma unroll
                for (int c = 0; c < 4; c++) a[r][c] = sSa[(gi0+r)*PAD + gj0 + c];

            float logsum = 0.f;
            for (int p = 0; p < NDIM; p++) {
                const int buf = p & 1;
                if ((p >> 2) == (tid >> 4)) {
                    const int pr = p - gi0;
#pragma unroll
                    for (int c = 0; c < 4; c++) s_row[buf][gj0 + c] = a[pr][c];
                }
                if ((p >> 2) == (tid & 15)) {
                    const int pc = p - gj0;
#pragma unroll
                    for (int r = 0; r < 4; r++) s_col[buf][gi0 + r] = a[r][pc];
                }
                __syncthreads();
                const float piv = s_row[buf][p];
                const float d = 1.0f / piv;
                if (tid == 0) logsum += logf(piv);
                float4 rowv = *(const float4*)&s_row[buf][gj0];
                float4 colv = *(const float4*)&s_col[buf][gi0];
                const float* rv = (const float*)&rowv;
                const float* cv = (const float*)&colv;
#pragma unroll
                for (int r = 0; r < 4; r++) {
                    const float aip = cv[r];
                    const bool ip = (gi0 + r == p);
#pragma unroll
                    for (int c = 0; c < 4; c++) {
                        const float apj = rv[c];
                        const bool jp = (gj0 + c == p);
                        float v = a[r][c] - aip * apj * d;
                        if (ip) v = apj * d;
                        if (jp) v = -aip * d;
                        if (ip && jp) v = d;
                        a[r][c] = v;
                    }
                }
            }
            if (tid == 0) g_pref[t] = -NDIM * HL2PI - 0.5f * logsum;
#pragma unroll
            for (int r = 0; r < 4; r++)
#pragma unroll
                for (int c = 0; c < 4; c++) sSa[(gi0+r)*PAD + gj0 + c] = a[r][c];
        }
        __syncthreads();

        mm64<true,true>(sT, sSa, sCW, nullptr, 1.f);                 // K^T
        __syncthreads();
        mm64_sym<true,true>(sP, sT, sCW, sP, -1.f, si0, sj0, s_act); // postP
        __syncthreads();

        // ---- store + convergence check ----
        float mymax = 0.f;
        const size_t off = (size_t)t * NDIM * NDIM;
        for (int idx = tid; idx < NDIM*NDIM; idx += blockDim.x) {
            int i = idx >> 6, j = idx & 63;
            float v = sP[i*PAD + j];
            if (t >= 1) mymax = fmaxf(mymax, fabsf(v - sPrev[i*PAD + j]));
            sPrev[i*PAD + j] = v;
            g_postP[off + idx] = v;
            g_KT[off + idx]    = sT[i*PAD + j];
            g_SI[off + idx]    = sSa[i*PAD + j];
        }
        s_red[tid] = mymax;
        __syncthreads();
        for (int s = 128; s > 0; s >>= 1) {
            if (tid < s) s_red[tid] = fmaxf(s_red[tid], s_red[tid + s]);
            __syncthreads();
        }
        if (t >= 1 && s_red[0] < 1e-5f) { tf = t; break; }
        __syncthreads();
    }
    if (tid == 0) g_tfreeze = tf;
}

// =======================================================================
// Phase 2 (fused): segmented mean/likelihood recursion + covariance bcast.
// Grid (NSEG, NB/4), 256 threads (4 batch lanes x 64). Each segment warms
// up W steps from zero state (contraction kills the error); W adapts to tf.
// =======================================================================
__global__ void means_kernel(const float* __restrict__ obs,
                             const float* __restrict__ pm0,
                             const float* __restrict__ db,
                             float* __restrict__ out_means,
                             float* __restrict__ out_covs,
                             float* __restrict__ out_ll,
                             int T, int C)
{
    extern __shared__ float ms[];
    float* sFH = ms;            // interleaved {WFT, WHFT}: [(k*64+j)*2 + {0,1}]
    float* sKS = ms + 8192;     // interleaved {KT_f, SI_f}
    float* sPP = ms + 16384;    // frozen posterior covariance
    __shared__ float vm[4][NDIM], vr[4][NDIM];
    __shared__ float sred[4][2];

    const int tid  = threadIdx.x;
    const int lane = tid >> 6;
    const int j    = tid & 63;
    const int seg  = blockIdx.x;
    const int b    = blockIdx.y * 4 + lane;

    const int t0 = seg * C;
    if (t0 > T) return;
    const int tend = min(t0 + C - 1, T);
    const int tf = g_tfreeze;

    {
        const float* KTf = g_KT    + (size_t)tf * NDIM * NDIM;
        const float* SIf = g_SI    + (size_t)tf * NDIM * NDIM;
        const float* PPf = g_postP + (size_t)tf * NDIM * NDIM;
        for (int idx = tid; idx < NDIM*NDIM; idx += 256) {
            sFH[idx*2]   = g_WFT[idx];
            sFH[idx*2+1] = g_WHFT[idx];
            sKS[idx*2]   = KTf[idx];
            sKS[idx*2+1] = SIf[idx];
            sPP[idx]     = PPf[idx];
        }
    }
    const float dbj = db[j], c2j = g_c2[j], o0j = g_o0[j], pm0j = pm0[j];
    const float pref_f = g_pref[tf];

    int W = 4 * tf + 16; if (W < 72) W = 72;
    int ts = t0 - W; if (ts < 0) ts = 0;

    vm[lane][j] = 0.f;
    __syncthreads();
    float* vml = vm[lane];
    float* vrl = vr[lane];

    for (int t = ts; t <= tend; t++) {
        const float y = obs[((size_t)t * NB + b) * NDIM + j];
        float pm, o;
        if (t == 0) {
            pm = pm0j; o = o0j;
        } else {
            float a0 = 0.f, a1 = 0.f, c0 = 0.f, c1 = 0.f;
#pragma unroll 8
            for (int k = 0; k < NDIM; k += 2) {
                float2 v  = *(const float2*)&vml[k];
                float2 w0 = *(const float2*)&sFH[(k*NDIM + j)*2];
                float2 w1 = *(const float2*)&sFH[((k+1)*NDIM + j)*2];
                a0 += v.x * w0.x; c0 += v.x * w0.y;
                a1 += v.y * w1.x; c1 += v.y * w1.y;
            }
            pm = a0 + a1 + dbj;
            o  = c0 + c1 + c2j;
        }
        const float r = y - o;
        vrl[j] = r;
        __syncthreads();

        float mu0 = 0.f, mu1 = 0.f, u0 = 0.f, u1 = 0.f;
        if (t >= tf) {
#pragma unroll 8
            for (int k = 0; k < NDIM; k += 2) {
                float2 rv = *(const float2*)&vrl[k];
                float2 w0 = *(const float2*)&sKS[(k*NDIM + j)*2];
                float2 w1 = *(const float2*)&sKS[((k+1)*NDIM + j)*2];
                mu0 += rv.x * w0.x; u0 += rv.x * w0.y;
                mu1 += rv.y * w1.x; u1 += rv.y * w1.y;
            }
        } else {
            const float* KTp = g_KT + (size_t)t * NDIM * NDIM;
            const float* SIp = g_SI + (size_t)t * NDIM * NDIM;
#pragma unroll 4
            for (int k = 0; k < NDIM; k += 2) {
                float r0 = vrl[k], r1 = vrl[k+1];
                mu0 += r0 * KTp[k*NDIM + j];     u0 += r0 * SIp[k*NDIM + j];
                mu1 += r1 * KTp[(k+1)*NDIM + j]; u1 += r1 * SIp[(k+1)*NDIM + j];
            }
        }
        const float mnew = pm + mu0 + mu1;
        const float u = u0 + u1;
        if (t >= t0) out_means[((size_t)t * NB + b) * NDIM + j] = mnew;
        vml[j] = mnew;

        float q = r * u;
#pragma unroll
        for (int o2 = 16; o2 > 0; o2 >>= 1) q += __shfl_down_sync(0xffffffffu, q, o2);
        if ((j & 31) == 0) sred[lane][j >> 5] = q;

        if (t >= t0) {
            float4* dst = (float4*)(out_covs + ((size_t)t * NB + b) * NDIM * NDIM);
            const float4* s4 = (t >= tf) ? (const float4*)sPP
                                         : (const float4*)(g_postP + (size_t)t * NDIM * NDIM);
#pragma unroll
            for (int e = 0; e < 16; e++) dst[j + e*64] = s4[j + e*64];
        }
        __syncthreads();
        if (j == 0 && t >= t0) {
            float pref = (t >= tf) ? pref_f : g_pref[t];
            out_ll[(size_t)t * NB + b] = pref - 0.5f * (sred[lane][0] + sred[lane][1]);
        }
    }
}

// =======================================================================
extern "C" void kernel_launch(void* const* d_in, const int* in_sizes, int n_in,
                              void* d_out, int out_size)
{
    int base = n_in - 9;
    if (base < 0) base = 0;

    const float* obs = (const float*)d_in[base + 0];
    const float* pm0 = (const float*)d_in[base + 1];
    const float* pc  = (const float*)d_in[base + 2];
    const float* Fw  = (const float*)d_in[base + 3];
    const float* db  = (const float*)d_in[base + 4];
    const float* dc  = (const float*)d_in[base + 5];
    const float* Hw  = (const float*)d_in[base + 6];
    const float* ob  = (const float*)d_in[base + 7];
    const float* oc  = (const float*)d_in[base + 8];

    int T = in_sizes[base + 0] / (NB * NDIM) - 1;
    if (T > MAXT) T = MAXT;
    if (T < 1) T = 1;

    float* out_means = (float*)d_out;
    float* out_covs  = out_means + (size_t)(T + 1) * NB * NDIM;
    float* out_ll    = out_covs  + (size_t)(T + 1) * NB * NDIM * NDIM;

    const int NSEG = 8;
    const int C = (T + 1 + NSEG - 1) / NSEG;

    cudaFuncSetAttribute(riccati_kernel,
                         cudaFuncAttributeMaxDynamicSharedMemorySize, R_SMEM);
    cudaFuncSetAttribute(means_kernel,
                         cudaFuncAttributeMaxDynamicSharedMemorySize, M_SMEM);

    riccati_kernel<<<1, 256, R_SMEM>>>(pc, Fw, dc, Hw, oc, pm0, db, ob, T);
    dim3 mg(NSEG, NB / 4);
    means_kernel<<<mg, 256, M_SMEM>>>(obs, pm0, db, out_means, out_covs, out_ll, T, C);
}

// round 5
// speedup vs baseline: 10.6186x; 1.3059x over previous
#include <cuda_runtime.h>
#include <math.h>

#define NDIM 64
#define NB 64
#define MAXT 512
#define PAD 65
#define NMAT (NDIM*PAD)
#define HL2PI 0.91893853320467274178f
#define R_SMEM (9*NMAT*4)
#define M_SMEM (3*8192*4)

// ---------------- static device scratch ----------------
__device__ float g_KT[(MAXT+1)*NDIM*NDIM];
__device__ float g_SI[(MAXT+1)*NDIM*NDIM];
__device__ float g_postP[(MAXT+1)*NDIM*NDIM];
__device__ float g_pref[MAXT+1];
__device__ float g_W4[2*NDIM*NDIM];   // packed {F^T,(HF)^T}: [((k>>1)*64+j)*4 + (k&1)*2 + {0,1}]
__device__ float g_K4[2*NDIM*NDIM];   // packed {K^T_f, SI_f}
__device__ float g_WU[2*NDIM*NDIM];   // packed {A^T, K^T_f} for folded warm-up
__device__ float g_c2[NDIM];
__device__ float g_o0[NDIM];
__device__ float g_d0[NDIM];
__device__ int   g_tfreeze;
__device__ int   g_Wwarm;

// ---------------- 64x64 matmul on PAD-strided smem, 256 threads ----------------
template<bool TA, bool TB>
__device__ __forceinline__ void mm64(float* C, const float* A, const float* B,
                                     const float* Cadd, float sgn)
{
    const int tid = threadIdx.x;
    const int i0 = (tid >> 4) << 2;
    const int j0 = (tid & 15) << 2;
    float acc[4][4];
#pragma unroll
    for (int r = 0; r < 4; r++)
#pragma unroll
        for (int c = 0; c < 4; c++) acc[r][c] = 0.f;
#pragma unroll 4
    for (int k = 0; k < NDIM; k++) {
        float a[4], b[4];
#pragma unroll
        for (int r = 0; r < 4; r++) a[r] = TA ? A[k*PAD + (i0+r)] : A[(i0+r)*PAD + k];
#pragma unroll
        for (int c = 0; c < 4; c++) b[c] = TB ? B[(j0+c)*PAD + k] : B[k*PAD + (j0+c)];
#pragma unroll
        for (int r = 0; r < 4; r++)
#pragma unroll
            for (int c = 0; c < 4; c++) acc[r][c] += a[r] * b[c];
    }
#pragma unroll
    for (int r = 0; r < 4; r++)
#pragma unroll
        for (int c = 0; c < 4; c++) {
            float base = Cadd ? Cadd[(i0+r)*PAD + (j0+c)] : 0.f;
            C[(i0+r)*PAD + (j0+c)] = base + sgn * acc[r][c];
        }
}

template<bool TA, bool TB>
__device__ __forceinline__ void mm64_sym(float* C, const float* A, const float* B,
                                         const float* Cadd, float sgn,
                                         int i0, int j0, bool act)
{
    if (!act) return;
    float acc[4][4];
#pragma unroll
    for (int r = 0; r < 4; r++)
#pragma unroll
        for (int c = 0; c < 4; c++) acc[r][c] = 0.f;
#pragma unroll 4
    for (int k = 0; k < NDIM; k++) {
        float a[4], b[4];
#pragma unroll
        for (int r = 0; r < 4; r++) a[r] = TA ? A[k*PAD + (i0+r)] : A[(i0+r)*PAD + k];
#pragma unroll
        for (int c = 0; c < 4; c++) b[c] = TB ? B[(j0+c)*PAD + k] : B[k*PAD + (j0+c)];
#pragma unroll
        for (int r = 0; r < 4; r++)
#pragma unroll
            for (int c = 0; c < 4; c++) acc[r][c] += a[r] * b[c];
    }
#pragma unroll
    for (int r = 0; r < 4; r++)
#pragma unroll
        for (int c = 0; c < 4; c++) {
            float base = Cadd ? Cadd[(i0+r)*PAD + (j0+c)] : 0.f;
            float v = base + sgn * acc[r][c];
            C[(i0+r)*PAD + (j0+c)] = v;
            if (i0 != j0) C[(j0+c)*PAD + (i0+r)] = v;
        }
}

__device__ __forceinline__ void ld_mat(float* dst, const float* __restrict__ src) {
    for (int idx = threadIdx.x; idx < NDIM*NDIM; idx += blockDim.x)
        dst[(idx >> 6)*PAD + (idx & 63)] = src[idx];
}

// =======================================================================
// Phase 1: Riccati recursion, one CTA. Publishes per-t gains, frozen
// packed matrices, and the measured warm-up length.
// =======================================================================
__global__ void riccati_kernel(const float* __restrict__ prior_chol,
                               const float* __restrict__ Fw,
                               const float* __restrict__ dyn_chol,
                               const float* __restrict__ Hw,
                               const float* __restrict__ obs_chol,
                               const float* __restrict__ pm0,
                               const float* __restrict__ db,
                               const float* __restrict__ ob,
                               int T)
{
    extern __shared__ float sm[];
    float* sP    = sm + 0*NMAT;
    float* sT    = sm + 1*NMAT;
    float* sCW   = sm + 2*NMAT;
    float* sSa   = sm + 3*NMAT;
    float* sF    = sm + 4*NMAT;
    float* sH    = sm + 5*NMAT;
    float* sQ    = sm + 6*NMAT;
    float* sR    = sm + 7*NMAT;
    float* sPrev = sm + 8*NMAT;
    __shared__ float s_red8[8];
    __shared__ float s_row[2][NDIM];
    __shared__ float s_col[2][NDIM];
    __shared__ float s_c2s[NDIM];
    __shared__ int   s_conv;
    __shared__ float s_ratio;

    const int tid = threadIdx.x;
    const int gi0 = (tid >> 4) << 2;
    const int gj0 = (tid & 15) << 2;

    int sbi = -1, sbj = 0;
    {
        int acc = 0;
#pragma unroll
        for (int r = 0; r < 16; r++) {
            int cnt = 16 - r;
            if (tid >= acc && tid < acc + cnt) { sbi = r; sbj = r + (tid - acc); }
            acc += cnt;
        }
    }
    const bool s_act = (sbi >= 0);
    const int si0 = sbi << 2, sj0 = sbj << 2;

    ld_mat(sF, Fw); ld_mat(sH, Hw); ld_mat(sT, dyn_chol);
    __syncthreads();
    mm64_sym<false,true>(sQ, sT, sT, nullptr, 1.f, si0, sj0, s_act);
    __syncthreads();
    ld_mat(sT, obs_chol);
    __syncthreads();
    mm64_sym<false,true>(sR, sT, sT, nullptr, 1.f, si0, sj0, s_act);
    __syncthreads();
    ld_mat(sT, prior_chol);
    __syncthreads();
    mm64_sym<false,true>(sP, sT, sT, nullptr, 1.f, si0, sj0, s_act);
    __syncthreads();

    // HF and packed weights for means kernel
    mm64<false,false>(sT, sH, sF, nullptr, 1.f);   // sT = HF
    __syncthreads();
    for (int idx = tid; idx < NDIM*NDIM; idx += 256) {
        int k = idx >> 6, j = idx & 63;
        int base = (((k >> 1)*64 + j) << 2) + ((k & 1) << 1);
        g_W4[base + 0] = sF[j*PAD + k];   // F^T
        g_W4[base + 1] = sT[j*PAD + k];   // (HF)^T
    }
    if (tid < NDIM) {
        float c = 0.f, o0 = 0.f;
        for (int k = 0; k < NDIM; k++) {
            float h = sH[tid*PAD + k];
            c  += h * db[k];
            o0 += h * pm0[k];
        }
        s_c2s[tid] = c + ob[tid];
        g_c2[tid] = c + ob[tid];
        g_o0[tid] = o0 + ob[tid];
    }
    __syncthreads();

    int tf = T;
    float rprev = 1e30f;   // only tid 0's copy matters
    for (int t = 0; t <= T; t++) {
        if (t > 0) {
            mm64<false,false>(sT, sF, sP, nullptr, 1.f);
            __syncthreads();
            mm64_sym<false,true>(sP, sT, sF, sQ, 1.f, si0, sj0, s_act);
            __syncthreads();
        }
        mm64<false,true>(sCW, sP, sH, nullptr, 1.f);
        __syncthreads();
        mm64_sym<false,false>(sSa, sH, sCW, sR, 1.f, si0, sj0, s_act);
        __syncthreads();

        // ---- register-resident Gauss-Jordan inversion of S ----
        {
            float a[4][4];
#pragma unroll
            for (int r = 0; r < 4; r++)
#pragma unroll
                for (int c = 0; c < 4; c++) a[r][c] = sSa[(gi0+r)*PAD + gj0 + c];

            float logsum = 0.f;
            for (int p = 0; p < NDIM; p++) {
                const int buf = p & 1;
                if ((p >> 2) == (tid >> 4)) {
                    const int pr = p - gi0;
#pragma unroll
                    for (int c = 0; c < 4; c++) s_row[buf][gj0 + c] = a[pr][c];
                }
                if ((p >> 2) == (tid & 15)) {
                    const int pc = p - gj0;
#pragma unroll
                    for (int r = 0; r < 4; r++) s_col[buf][gi0 + r] = a[r][pc];
                }
                __syncthreads();
                const float piv = s_row[buf][p];
                const float d = 1.0f / piv;
                if (tid == 0) logsum += logf(piv);
                float4 rowv = *(const float4*)&s_row[buf][gj0];
                float4 colv = *(const float4*)&s_col[buf][gi0];
                const float* rv = (const float*)&rowv;
                const float* cv = (const float*)&colv;
#pragma unroll
                for (int r = 0; r < 4; r++) {
                    const float aip = cv[r];
                    const bool ip = (gi0 + r == p);
#pragma unroll
                    for (int c = 0; c < 4; c++) {
                        const float apj = rv[c];
                        const bool jp = (gj0 + c == p);
                        float v = a[r][c] - aip * apj * d;
                        if (ip) v = apj * d;
                        if (jp) v = -aip * d;
                        if (ip && jp) v = d;
                        a[r][c] = v;
                    }
                }
            }
            if (tid == 0) g_pref[t] = -NDIM * HL2PI - 0.5f * logsum;
#pragma unroll
            for (int r = 0; r < 4; r++)
#pragma unroll
                for (int c = 0; c < 4; c++) sSa[(gi0+r)*PAD + gj0 + c] = a[r][c];
        }
        __syncthreads();

        mm64<true,true>(sT, sSa, sCW, nullptr, 1.f);
        __syncthreads();
        mm64_sym<true,true>(sP, sT, sCW, sP, -1.f, si0, sj0, s_act);
        __syncthreads();

        // ---- store + convergence check (2 syncs) ----
        float mymax = 0.f;
        const size_t off = (size_t)t * NDIM * NDIM;
        for (int idx = tid; idx < NDIM*NDIM; idx += 256) {
            int i = idx >> 6, j = idx & 63;
            float v = sP[i*PAD + j];
            mymax = fmaxf(mymax, fabsf(v - sPrev[i*PAD + j]));
            sPrev[i*PAD + j] = v;
            g_postP[off + idx] = v;
            g_KT[off + idx]    = sT[i*PAD + j];
            g_SI[off + idx]    = sSa[i*PAD + j];
        }
#pragma unroll
        for (int o = 16; o > 0; o >>= 1)
            mymax = fmaxf(mymax, __shfl_xor_sync(0xffffffffu, mymax, o));
        if ((tid & 31) == 0) s_red8[tid >> 5] = mymax;
        __syncthreads();
        if (tid == 0) {
            float mx = s_red8[0];
#pragma unroll
            for (int i = 1; i < 8; i++) mx = fmaxf(mx, s_red8[i]);
            s_ratio = mx / fmaxf(rprev, 1e-30f);
            rprev = mx;
            s_conv = (t >= 1 && mx < 3e-5f) ? 1 : 0;
        }
        __syncthreads();
        if (s_conv) { tf = t; break; }
    }

    // ---- epilogue: frozen packed matrices, folded warm-up matrices ----
    if (tid == 0) {
        g_tfreeze = tf;
        float r2 = fminf(fmaxf(s_ratio, 0.01f), 0.95f);
        float lnrho = 0.5f * logf(r2);
        int W = (int)(11.6f / (-lnrho)) + 4;
        if (W < 16) W = 16;
        if (W > 200) W = 200;
        g_Wwarm = W;
    }
    mm64<false,false>(sCW, sH, sF, nullptr, 1.f);   // HF
    __syncthreads();
    mm64<true,false>(sR, sCW, sT, nullptr, 1.f);    // sR[k][j] = sum_m HF[m][k] K[j][m]
    __syncthreads();
    for (int idx = tid; idx < NDIM*NDIM; idx += 256) {
        int k = idx >> 6, j = idx & 63;
        float at = sF[j*PAD + k] - sR[k*PAD + j];   // A^T[k][j], A = F - K*HF
        float kt = sT[k*PAD + j];
        float si = sSa[k*PAD + j];
        int base = (((k >> 1)*64 + j) << 2) + ((k & 1) << 1);
        g_WU[base + 0] = at; g_WU[base + 1] = kt;
        g_K4[base + 0] = kt; g_K4[base + 1] = si;
    }
    if (tid < NDIM) {
        float s = 0.f;
        for (int k = 0; k < NDIM; k++) s += sT[k*PAD + tid] * s_c2s[k];
        g_d0[tid] = db[tid] - s;   // d0 = db - K*c2
    }
}

// =======================================================================
// Phase 2 (fused): segmented mean/likelihood recursion + covariance bcast.
// Grid (NSEG, 16), 256 threads (4 batches x 64). Frozen warm-up uses the
// folded recursion m = A m + K y + d0 with runtime-measured length W.
// =======================================================================
__global__ void __launch_bounds__(256, 2)
means_kernel(const float* __restrict__ obs,
             const float* __restrict__ pm0,
             const float* __restrict__ db,
             float* __restrict__ out_means,
             float* __restrict__ out_covs,
             float* __restrict__ out_ll,
             int T, int C)
{
    extern __shared__ float ms[];
    float* sW4 = ms;            // 8192 floats
    float* sK4 = ms + 8192;
    float* sWU = ms + 16384;
    __shared__ __align__(16) float vmbuf[2][4][NDIM];
    __shared__ __align__(16) float vybuf[2][4][NDIM];
    __shared__ __align__(16) float vr[4][NDIM];
    __shared__ float sred[4][2];

    const int tid  = threadIdx.x;
    const int lane = tid >> 6;
    const int j    = tid & 63;
    const int seg  = blockIdx.x;
    const int b    = blockIdx.y * 4 + lane;

    const int t0 = seg * C;
    if (t0 > T) return;
    const int tend = min(t0 + C - 1, T);
    const int tf = g_tfreeze;
    const int W = g_Wwarm;

    for (int idx = tid; idx < 8192; idx += 256) {
        sW4[idx] = g_W4[idx];
        sK4[idx] = g_K4[idx];
        sWU[idx] = g_WU[idx];
    }
    const float dbj = db[j], c2j = g_c2[j], o0j = g_o0[j];
    const float pm0j = pm0[j], d0j = g_d0[j];
    const float pref_f = g_pref[tf];

    // frozen covariance cached in registers
    float4 covr[16];
    {
        const float4* pf = (const float4*)(g_postP + (size_t)tf * NDIM * NDIM);
#pragma unroll
        for (int e = 0; e < 16; e++) covr[e] = pf[j + e*64];
    }

    int ts = t0 - W;
    const bool frozen_warm = (t0 > 0) && (ts >= tf);

    int p = 0;
    vmbuf[0][lane][j] = 0.f;
    vmbuf[1][lane][j] = 0.f;
    if (frozen_warm) vybuf[0][lane][j] = obs[((size_t)ts * NB + b) * NDIM + j];
    __syncthreads();

    if (frozen_warm) {
        for (int t = ts; t < t0; t++) {
            vybuf[p^1][lane][j] = obs[((size_t)(t+1) * NB + b) * NDIM + j];
            const float* vml = vmbuf[p][lane];
            const float* vyl = vybuf[p][lane];
            float m0 = 0.f, m1 = 0.f;
#pragma unroll
            for (int k = 0; k < NDIM; k += 4) {
                float4 v  = *(const float4*)&vml[k];
                float4 yv = *(const float4*)&vyl[k];
                float4 w0 = *(const float4*)&sWU[((k>>1)*64 + j) << 2];
                float4 w1 = *(const float4*)&sWU[(((k>>1)+1)*64 + j) << 2];
                m0 += v.x*w0.x + yv.x*w0.y;
                m1 += v.y*w0.z + yv.y*w0.w;
                m0 += v.z*w1.x + yv.z*w1.y;
                m1 += v.w*w1.z + yv.w*w1.w;
            }
            vmbuf[p^1][lane][j] = m0 + m1 + d0j;
            p ^= 1;
            __syncthreads();
        }
    }

    const int tstart = frozen_warm ? t0 : 0;
    for (int t = tstart; t <= tend; t++) {
        const float y = obs[((size_t)t * NB + b) * NDIM + j];
        const float* vml = vmbuf[p][lane];
        float pm, o;
        if (t == 0) {
            pm = pm0j; o = o0j;
        } else {
            float a0 = 0.f, a1 = 0.f, c0 = 0.f, c1 = 0.f;
#pragma unroll
            for (int k = 0; k < NDIM; k += 4) {
                float4 v  = *(const float4*)&vml[k];
                float4 w0 = *(const float4*)&sW4[((k>>1)*64 + j) << 2];
                float4 w1 = *(const float4*)&sW4[(((k>>1)+1)*64 + j) << 2];
                a0 += v.x*w0.x; c0 += v.x*w0.y;
                a1 += v.y*w0.z; c1 += v.y*w0.w;
                a0 += v.z*w1.x; c0 += v.z*w1.y;
                a1 += v.w*w1.z; c1 += v.w*w1.w;
            }
            pm = a0 + a1 + dbj;
            o  = c0 + c1 + c2j;
        }
        const float r = y - o;
        vr[lane][j] = r;
        __syncthreads();

        const float* vrl = vr[lane];
        float mu0 = 0.f, mu1 = 0.f, u0 = 0.f, u1 = 0.f;
        if (t >= tf) {
#pragma unroll
            for (int k = 0; k < NDIM; k += 4) {
                float4 r4 = *(const float4*)&vrl[k];
                float4 w0 = *(const float4*)&sK4[((k>>1)*64 + j) << 2];
                float4 w1 = *(const float4*)&sK4[(((k>>1)+1)*64 + j) << 2];
                mu0 += r4.x*w0.x; u0 += r4.x*w0.y;
                mu1 += r4.y*w0.z; u1 += r4.y*w0.w;
                mu0 += r4.z*w1.x; u0 += r4.z*w1.y;
                mu1 += r4.w*w1.z; u1 += r4.w*w1.w;
            }
        } else {
            const float* KTp = g_KT + (size_t)t * NDIM * NDIM;
            const float* SIp = g_SI + (size_t)t * NDIM * NDIM;
#pragma unroll 4
            for (int k = 0; k < NDIM; k += 2) {
                float r0 = vrl[k], r1 = vrl[k+1];
                mu0 += r0 * KTp[k*NDIM + j];     u0 += r0 * SIp[k*NDIM + j];
                mu1 += r1 * KTp[(k+1)*NDIM + j]; u1 += r1 * SIp[(k+1)*NDIM + j];
            }
        }
        const float mnew = pm + mu0 + mu1;
        vmbuf[p^1][lane][j] = mnew;

        if (t >= t0) {
            out_means[((size_t)t * NB + b) * NDIM + j] = mnew;
            float q = r * (u0 + u1);
#pragma unroll
            for (int o2 = 16; o2 > 0; o2 >>= 1)
                q += __shfl_down_sync(0xffffffffu, q, o2);
            if ((j & 31) == 0) sred[lane][j >> 5] = q;

            float4* dst = (float4*)(out_covs + ((size_t)t * NB + b) * NDIM * NDIM);
            if (t >= tf) {
#pragma unroll
                for (int e = 0; e < 16; e++) dst[j + e*64] = covr[e];
            } else {
                const float4* s4 = (const float4*)(g_postP + (size_t)t * NDIM * NDIM);
#pragma unroll
                for (int e = 0; e < 16; e++) dst[j + e*64] = s4[j + e*64];
            }
        }
        __syncthreads();
        if (j == 0 && t >= t0) {
            float pref = (t >= tf) ? pref_f : g_pref[t];
            out_ll[(size_t)t * NB + b] = pref - 0.5f * (sred[lane][0] + sred[lane][1]);
        }
        p ^= 1;
    }
}

// =======================================================================
extern "C" void kernel_launch(void* const* d_in, const int* in_sizes, int n_in,
                              void* d_out, int out_size)
{
    int base = n_in - 9;
    if (base < 0) base = 0;

    const float* obs = (const float*)d_in[base + 0];
    const float* pm0 = (const float*)d_in[base + 1];
    const float* pc  = (const float*)d_in[base + 2];
    const float* Fw  = (const float*)d_in[base + 3];
    const float* db  = (const float*)d_in[base + 4];
    const float* dc  = (const float*)d_in[base + 5];
    const float* Hw  = (const float*)d_in[base + 6];
    const float* ob  = (const float*)d_in[base + 7];
    const float* oc  = (const float*)d_in[base + 8];

    int T = in_sizes[base + 0] / (NB * NDIM) - 1;
    if (T > MAXT) T = MAXT;
    if (T < 1) T = 1;

    float* out_means = (float*)d_out;
    float* out_covs  = out_means + (size_t)(T + 1) * NB * NDIM;
    float* out_ll    = out_covs  + (size_t)(T + 1) * NB * NDIM * NDIM;

    const int NSEG = 16;
    const int C = (T + 1 + NSEG - 1) / NSEG;

    cudaFuncSetAttribute(riccati_kernel,
                         cudaFuncAttributeMaxDynamicSharedMemorySize, R_SMEM);
    cudaFuncSetAttribute(means_kernel,
                         cudaFuncAttributeMaxDynamicSharedMemorySize, M_SMEM);

    riccati_kernel<<<1, 256, R_SMEM>>>(pc, Fw, dc, Hw, oc, pm0, db, ob, T);
    dim3 mg(NSEG, NB / 4);
    means_kernel<<<mg, 256, M_SMEM>>>(obs, pm0, db, out_means, out_covs, out_ll, T, C);
}